// round 1
// baseline (speedup 1.0000x reference)
#include <cuda_runtime.h>

// SAGE_68281390072709 — 2-layer GraphSAGE, fp32.
// Inputs (metadata order): x[50000,128], src[800000], dst[800000],
//   W_self0[128,128], W_neigh0[128,128], b0[128],
//   W_self1[128,41],  W_neigh1[128,41],  b1[41]
// Output: [50000, 41] float32.
//
// Strategy:
//  - deg[i] = #edges into i (float, atomics)
//  - Layer0: S0 = x@W_self0 -> written directly into g_h
//            Y0 = x@W_neigh0
//            agg0[dst] += Y0[src] (atomics, warp = 1 edge, 512B coalesced)
//            g_h = relu(g_h + agg0/max(deg,1) + b0)   (in place)
//  - Layer1: S1 = h@W_self1 -> written directly into d_out
//            Y1 = h@W_neigh1
//            agg1[dst] += Y1[src] (scalar atomics over 41 feats)
//            d_out += agg1/max(deg,1) + b1            (in place)

#define NN 50000
#define EE 800000
#define F0 128
#define F1 128
#define C1 41

__device__ float g_Y0[NN * F1];
__device__ float g_agg0[NN * F1];
__device__ float g_h[NN * F1];
__device__ float g_Y1[NN * C1];
__device__ float g_agg1[NN * C1];
__device__ float g_deg[NN];

// ---------------------------------------------------------------------------
// zero the accumulators (must run every replay)
// ---------------------------------------------------------------------------
__global__ void zero_all_kernel() {
    int i = blockIdx.x * blockDim.x + threadIdx.x;
    int stride = gridDim.x * blockDim.x;
    float4 z = make_float4(0.f, 0.f, 0.f, 0.f);
    float4* a0 = reinterpret_cast<float4*>(g_agg0);
    float4* a1 = reinterpret_cast<float4*>(g_agg1);
    float4* dg = reinterpret_cast<float4*>(g_deg);
    const int n0 = (NN * F1) / 4;   // 1,600,000
    const int n1 = (NN * C1) / 4;   // 512,500
    const int nd = NN / 4;          // 12,500
    for (int j = i; j < n0; j += stride) a0[j] = z;
    for (int j = i; j < n1; j += stride) a1[j] = z;
    for (int j = i; j < nd; j += stride) dg[j] = z;
}

// ---------------------------------------------------------------------------
// degree
// ---------------------------------------------------------------------------
__global__ void degree_kernel(const int* __restrict__ dst, int E) {
    int i = blockIdx.x * blockDim.x + threadIdx.x;
    if (i < E) atomicAdd(&g_deg[dst[i]], 1.0f);
}

// ---------------------------------------------------------------------------
// tiled fp32 SGEMM: C[M,N] = A[M,K] @ B[K,N]; K multiple of 16, 16B-aligned A rows
// BM=64 BN=64 BK=16, 256 threads, 4x4 register tile per thread
// ---------------------------------------------------------------------------
template <int BM, int BN, int BK, int TM, int TN>
__global__ void sgemm_kernel(const float* __restrict__ A,
                             const float* __restrict__ B,
                             float* __restrict__ C,
                             int M, int N, int K) {
    __shared__ float As[BK][BM];
    __shared__ float Bs[BK][BN + 1];

    const int tid = threadIdx.x;                 // 256 threads
    const int m0 = blockIdx.x * BM;
    const int n0 = blockIdx.y * BN;
    const int tx = tid % (BN / TN);              // 0..15
    const int ty = tid / (BN / TN);              // 0..15

    // A-load mapping: each thread loads float4 along K
    const int a_row = tid / (BK / 4);            // 0..63
    const int a_col = (tid % (BK / 4)) * 4;      // 0,4,8,12
    // B-load mapping: each thread loads 4 scalars along N (guarded)
    const int b_row = tid / (BN / 4);            // 0..15
    const int b_col = (tid % (BN / 4)) * 4;      // 0..60

    float acc[TM][TN];
#pragma unroll
    for (int i = 0; i < TM; i++)
#pragma unroll
        for (int j = 0; j < TN; j++) acc[i][j] = 0.f;

    for (int k0 = 0; k0 < K; k0 += BK) {
        float4 av = make_float4(0.f, 0.f, 0.f, 0.f);
        int gm = m0 + a_row;
        if (gm < M)
            av = *reinterpret_cast<const float4*>(A + (long)gm * K + k0 + a_col);
        As[a_col + 0][a_row] = av.x;
        As[a_col + 1][a_row] = av.y;
        As[a_col + 2][a_row] = av.z;
        As[a_col + 3][a_row] = av.w;

#pragma unroll
        for (int j = 0; j < 4; j++) {
            int gn = n0 + b_col + j;
            Bs[b_row][b_col + j] = (gn < N) ? B[(long)(k0 + b_row) * N + gn] : 0.f;
        }
        __syncthreads();

#pragma unroll
        for (int k = 0; k < BK; k++) {
            float ar[TM], br[TN];
#pragma unroll
            for (int i = 0; i < TM; i++) ar[i] = As[k][ty * TM + i];
#pragma unroll
            for (int j = 0; j < TN; j++) br[j] = Bs[k][tx * TN + j];
#pragma unroll
            for (int i = 0; i < TM; i++)
#pragma unroll
                for (int j = 0; j < TN; j++) acc[i][j] += ar[i] * br[j];
        }
        __syncthreads();
    }

#pragma unroll
    for (int i = 0; i < TM; i++) {
        int gm = m0 + ty * TM + i;
        if (gm >= M) continue;
#pragma unroll
        for (int j = 0; j < TN; j++) {
            int gn = n0 + tx * TN + j;
            if (gn < N) C[(long)gm * N + gn] = acc[i][j];
        }
    }
}

// ---------------------------------------------------------------------------
// layer-0 aggregation: one warp per edge, float4 per lane-group
// ---------------------------------------------------------------------------
__global__ void agg128_kernel(const int* __restrict__ src,
                              const int* __restrict__ dst, int E) {
    int idx = blockIdx.x * blockDim.x + threadIdx.x;
    if (idx >= E * 32) return;
    int e = idx >> 5;
    int c = idx & 31;
    int s = src[e];
    int d = dst[e];
    float4 v = *reinterpret_cast<const float4*>(g_Y0 + (long)s * F1 + c * 4);
    float* o = g_agg0 + (long)d * F1 + c * 4;
    atomicAdd(o + 0, v.x);
    atomicAdd(o + 1, v.y);
    atomicAdd(o + 2, v.z);
    atomicAdd(o + 3, v.w);
}

// ---------------------------------------------------------------------------
// layer-0 finalize: h = relu(h + agg0/max(deg,1) + b0), in place, float4
// ---------------------------------------------------------------------------
__global__ void finalize0_kernel(const float* __restrict__ b0) {
    int idx = blockIdx.x * blockDim.x + threadIdx.x;
    if (idx >= NN * (F1 / 4)) return;
    int node = idx >> 5;
    int c = idx & 31;
    float invd = 1.0f / fmaxf(g_deg[node], 1.0f);
    float4 h = *reinterpret_cast<const float4*>(g_h + (long)node * F1 + c * 4);
    float4 a = *reinterpret_cast<const float4*>(g_agg0 + (long)node * F1 + c * 4);
    float4 b = *reinterpret_cast<const float4*>(b0 + c * 4);
    h.x = fmaxf(h.x + a.x * invd + b.x, 0.f);
    h.y = fmaxf(h.y + a.y * invd + b.y, 0.f);
    h.z = fmaxf(h.z + a.z * invd + b.z, 0.f);
    h.w = fmaxf(h.w + a.w * invd + b.w, 0.f);
    *reinterpret_cast<float4*>(g_h + (long)node * F1 + c * 4) = h;
}

// ---------------------------------------------------------------------------
// layer-1 aggregation: scalar, one thread per (edge, feature)
// ---------------------------------------------------------------------------
__global__ void agg41_kernel(const int* __restrict__ src,
                             const int* __restrict__ dst, int E) {
    int idx = blockIdx.x * blockDim.x + threadIdx.x;
    if (idx >= E * C1) return;
    int e = idx / C1;            // compiler: mul-shift (constant divisor)
    int f = idx - e * C1;
    int s = src[e];
    int d = dst[e];
    atomicAdd(&g_agg1[(long)d * C1 + f], g_Y1[(long)s * C1 + f]);
}

// ---------------------------------------------------------------------------
// layer-1 finalize: out += agg1/max(deg,1) + b1, in place (out holds S1)
// ---------------------------------------------------------------------------
__global__ void finalize1_kernel(float* __restrict__ out,
                                 const float* __restrict__ b1) {
    int idx = blockIdx.x * blockDim.x + threadIdx.x;
    if (idx >= NN * C1) return;
    int node = idx / C1;
    int f = idx - node * C1;
    float invd = 1.0f / fmaxf(g_deg[node], 1.0f);
    out[idx] = out[idx] + g_agg1[idx] * invd + b1[f];
}

// ---------------------------------------------------------------------------
extern "C" void kernel_launch(void* const* d_in, const int* in_sizes, int n_in,
                              void* d_out, int out_size) {
    const float* x       = (const float*)d_in[0];
    const int*   src     = (const int*)d_in[1];
    const int*   dst     = (const int*)d_in[2];
    const float* W_self0 = (const float*)d_in[3];
    const float* W_neigh0= (const float*)d_in[4];
    const float* b0      = (const float*)d_in[5];
    const float* W_self1 = (const float*)d_in[6];
    const float* W_neigh1= (const float*)d_in[7];
    const float* b1      = (const float*)d_in[8];
    float* out = (float*)d_out;

    const int M = in_sizes[0] / F0;   // 50000
    const int E = in_sizes[1];        // 800000

    // scratch pointers (device globals; addresses resolved at compile time in kernels)
    float* dY0;  cudaGetSymbolAddress((void**)&dY0, g_Y0);
    float* dY1;  cudaGetSymbolAddress((void**)&dY1, g_Y1);
    float* dH;   cudaGetSymbolAddress((void**)&dH, g_h);

    constexpr int BM = 64, BN = 64, BK = 16, TM = 4, TN = 4;
    dim3 thr(256);

    // 0) zero accumulators + degree
    zero_all_kernel<<<2048, 256>>>();
    degree_kernel<<<(E + 255) / 256, 256>>>(dst, E);

    // 1) layer-0 GEMMs
    dim3 g0((M + BM - 1) / BM, (F1 + BN - 1) / BN);
    sgemm_kernel<BM, BN, BK, TM, TN><<<g0, thr>>>(x, W_self0, dH, M, F1, F0);
    sgemm_kernel<BM, BN, BK, TM, TN><<<g0, thr>>>(x, W_neigh0, dY0, M, F1, F0);

    // 2) layer-0 aggregation + finalize
    agg128_kernel<<<(E * 32 + 255) / 256, 256>>>(src, dst, E);
    finalize0_kernel<<<(M * (F1 / 4) + 255) / 256, 256>>>(b0);

    // 3) layer-1 GEMMs
    dim3 g1((M + BM - 1) / BM, (C1 + BN - 1) / BN);
    sgemm_kernel<BM, BN, BK, TM, TN><<<g1, thr>>>(dH, W_self1, out, M, C1, F1);
    sgemm_kernel<BM, BN, BK, TM, TN><<<g1, thr>>>(dH, W_neigh1, dY1, M, C1, F1);

    // 4) layer-1 aggregation + finalize
    agg41_kernel<<<(E * C1 + 255) / 256, 256>>>(src, dst, E);
    finalize1_kernel<<<(M * C1 + 255) / 256, 256>>>(out, b1);
}

// round 2
// speedup vs baseline: 1.2912x; 1.2912x over previous
#include <cuda_runtime.h>
#include <cstdint>

// SAGE_68281390072709 — 2-layer GraphSAGE, fp32, tf32 tensor-core GEMMs.
// Layer0: h = relu(x@Ws0 + mean_agg(x@Wn0) + b0)
// Layer1: out = h@Ws1 + mean_agg(h@Wn1) + b1

#define NN 50000
#define EE 800000
#define F0 128
#define F1 128
#define C1 41

__device__ float g_Y0[NN * F1];
__device__ float g_agg0[NN * F1];
__device__ float g_h[NN * F1];
__device__ float g_Y1[NN * C1];
__device__ float g_agg1[NN * C1];
__device__ float g_deg[NN];

// ---------------------------------------------------------------------------
__global__ void zero_all_kernel() {
    int i = blockIdx.x * blockDim.x + threadIdx.x;
    int stride = gridDim.x * blockDim.x;
    float4 z = make_float4(0.f, 0.f, 0.f, 0.f);
    float4* a0 = reinterpret_cast<float4*>(g_agg0);
    float4* a1 = reinterpret_cast<float4*>(g_agg1);
    float4* dg = reinterpret_cast<float4*>(g_deg);
    const int n0 = (NN * F1) / 4;
    const int n1 = (NN * C1) / 4;
    const int nd = NN / 4;
    for (int j = i; j < n0; j += stride) a0[j] = z;
    for (int j = i; j < n1; j += stride) a1[j] = z;
    for (int j = i; j < nd; j += stride) dg[j] = z;
}

__global__ void degree_kernel(const int* __restrict__ dst, int E) {
    int i = blockIdx.x * blockDim.x + threadIdx.x;
    if (i < E) atomicAdd(&g_deg[dst[i]], 1.0f);
}

// ---------------------------------------------------------------------------
// tf32 tensor-core GEMM: C[M,N] = A[M,K] @ B[K,N], fp32 in/out, tf32 mma.
// BM=128, BN=64, BK=16, 256 threads (8 warps, 4x2), warp tile 32x32.
// ---------------------------------------------------------------------------
__device__ __forceinline__ uint32_t f2tf32(float x) {
    uint32_t r;
    asm("cvt.rna.tf32.f32 %0, %1;" : "=r"(r) : "f"(x));
    return r;
}

__device__ __forceinline__ void mma_tf32(float* c, const uint32_t* a, const uint32_t* b) {
    asm volatile(
        "mma.sync.aligned.m16n8k8.row.col.f32.tf32.tf32.f32 "
        "{%0,%1,%2,%3}, {%4,%5,%6,%7}, {%8,%9}, {%0,%1,%2,%3};"
        : "+f"(c[0]), "+f"(c[1]), "+f"(c[2]), "+f"(c[3])
        : "r"(a[0]), "r"(a[1]), "r"(a[2]), "r"(a[3]), "r"(b[0]), "r"(b[1]));
}

template <bool GUARD_N>
__global__ void __launch_bounds__(256)
mma_gemm_kernel(const float* __restrict__ A, const float* __restrict__ B,
                float* __restrict__ C, int M, int N, int K) {
    constexpr int BM = 128, BN = 64, BK = 16;
    // padded strides chosen for conflict-free fragment LDS:
    //  As stride 20: (20*g + t) mod 32 all distinct
    //  Bs stride 72: ( 8*t + g) mod 32 all distinct
    __shared__ uint32_t As[BM][BK + 4];
    __shared__ uint32_t Bs[BK][BN + 8];

    const int tid = threadIdx.x;
    const int lane = tid & 31;
    const int wid = tid >> 5;
    const int g = lane >> 2;   // group id 0..7
    const int t = lane & 3;    // thread-in-group 0..3
    const int wm = (wid >> 1) * 32;  // warp row offset in tile
    const int wn = (wid & 1) * 32;   // warp col offset in tile
    const int m0 = blockIdx.x * BM;
    const int n0 = blockIdx.y * BN;

    float acc[2][4][4];
#pragma unroll
    for (int mf = 0; mf < 2; mf++)
#pragma unroll
        for (int nf = 0; nf < 4; nf++)
#pragma unroll
            for (int i = 0; i < 4; i++) acc[mf][nf][i] = 0.f;

    for (int k0 = 0; k0 < K; k0 += BK) {
        // --- load A tile: 128x16 floats, 2 float4 per thread ---
#pragma unroll
        for (int i = 0; i < 2; i++) {
            int v = tid + i * 256;      // vec4 index 0..511
            int row = v >> 2;           // 0..127
            int c4 = (v & 3) * 4;       // 0,4,8,12
            float4 av = make_float4(0.f, 0.f, 0.f, 0.f);
            int gm = m0 + row;
            if (gm < M)
                av = *reinterpret_cast<const float4*>(A + (long)gm * K + k0 + c4);
            As[row][c4 + 0] = f2tf32(av.x);
            As[row][c4 + 1] = f2tf32(av.y);
            As[row][c4 + 2] = f2tf32(av.z);
            As[row][c4 + 3] = f2tf32(av.w);
        }
        // --- load B tile: 16x64 floats, 1 float4 per thread ---
        {
            int row = tid >> 4;         // 0..15 (k)
            int c4 = (tid & 15) * 4;    // 0..60 (n)
            if (GUARD_N) {
#pragma unroll
                for (int j = 0; j < 4; j++) {
                    int gn = n0 + c4 + j;
                    float bv = (gn < N) ? B[(long)(k0 + row) * N + gn] : 0.f;
                    Bs[row][c4 + j] = f2tf32(bv);
                }
            } else {
                float4 bv = *reinterpret_cast<const float4*>(B + (long)(k0 + row) * N + n0 + c4);
                Bs[row][c4 + 0] = f2tf32(bv.x);
                Bs[row][c4 + 1] = f2tf32(bv.y);
                Bs[row][c4 + 2] = f2tf32(bv.z);
                Bs[row][c4 + 3] = f2tf32(bv.w);
            }
        }
        __syncthreads();

#pragma unroll
        for (int ks = 0; ks < BK; ks += 8) {
            uint32_t a[2][4], b[4][2];
#pragma unroll
            for (int mf = 0; mf < 2; mf++) {
                int r = wm + mf * 16;
                a[mf][0] = As[r + g][ks + t];
                a[mf][1] = As[r + g + 8][ks + t];
                a[mf][2] = As[r + g][ks + t + 4];
                a[mf][3] = As[r + g + 8][ks + t + 4];
            }
#pragma unroll
            for (int nf = 0; nf < 4; nf++) {
                int c = wn + nf * 8 + g;
                b[nf][0] = Bs[ks + t][c];
                b[nf][1] = Bs[ks + t + 4][c];
            }
#pragma unroll
            for (int mf = 0; mf < 2; mf++)
#pragma unroll
                for (int nf = 0; nf < 4; nf++)
                    mma_tf32(acc[mf][nf], a[mf], b[nf]);
        }
        __syncthreads();
    }

    // --- store C ---
#pragma unroll
    for (int mf = 0; mf < 2; mf++) {
#pragma unroll
        for (int nf = 0; nf < 4; nf++) {
            int row0 = m0 + wm + mf * 16 + g;
            int col0 = n0 + wn + nf * 8 + 2 * t;
#pragma unroll
            for (int rr = 0; rr < 2; rr++) {
                int row = row0 + rr * 8;
                if (row >= M) continue;
                float* cp = C + (long)row * N + col0;
                if (!GUARD_N || col0 < N)     cp[0] = acc[mf][nf][rr * 2 + 0];
                if (!GUARD_N || col0 + 1 < N) cp[1] = acc[mf][nf][rr * 2 + 1];
            }
        }
    }
}

// ---------------------------------------------------------------------------
// layer-0 aggregation: one warp per edge, float4 per lane-group
// ---------------------------------------------------------------------------
__global__ void agg128_kernel(const int* __restrict__ src,
                              const int* __restrict__ dst, int E) {
    int idx = blockIdx.x * blockDim.x + threadIdx.x;
    if (idx >= E * 32) return;
    int e = idx >> 5;
    int c = idx & 31;
    int s = src[e];
    int d = dst[e];
    float4 v = *reinterpret_cast<const float4*>(g_Y0 + (long)s * F1 + c * 4);
    float* o = g_agg0 + (long)d * F1 + c * 4;
    atomicAdd(o + 0, v.x);
    atomicAdd(o + 1, v.y);
    atomicAdd(o + 2, v.z);
    atomicAdd(o + 3, v.w);
}

__global__ void finalize0_kernel(const float* __restrict__ b0) {
    int idx = blockIdx.x * blockDim.x + threadIdx.x;
    if (idx >= NN * (F1 / 4)) return;
    int node = idx >> 5;
    int c = idx & 31;
    float invd = 1.0f / fmaxf(g_deg[node], 1.0f);
    float4 h = *reinterpret_cast<const float4*>(g_h + (long)node * F1 + c * 4);
    float4 a = *reinterpret_cast<const float4*>(g_agg0 + (long)node * F1 + c * 4);
    float4 b = *reinterpret_cast<const float4*>(b0 + c * 4);
    h.x = fmaxf(h.x + a.x * invd + b.x, 0.f);
    h.y = fmaxf(h.y + a.y * invd + b.y, 0.f);
    h.z = fmaxf(h.z + a.z * invd + b.z, 0.f);
    h.w = fmaxf(h.w + a.w * invd + b.w, 0.f);
    *reinterpret_cast<float4*>(g_h + (long)node * F1 + c * 4) = h;
}

__global__ void agg41_kernel(const int* __restrict__ src,
                             const int* __restrict__ dst, int E) {
    int idx = blockIdx.x * blockDim.x + threadIdx.x;
    if (idx >= E * C1) return;
    int e = idx / C1;
    int f = idx - e * C1;
    int s = src[e];
    int d = dst[e];
    atomicAdd(&g_agg1[(long)d * C1 + f], g_Y1[(long)s * C1 + f]);
}

__global__ void finalize1_kernel(float* __restrict__ out,
                                 const float* __restrict__ b1) {
    int idx = blockIdx.x * blockDim.x + threadIdx.x;
    if (idx >= NN * C1) return;
    int node = idx / C1;
    int f = idx - node * C1;
    float invd = 1.0f / fmaxf(g_deg[node], 1.0f);
    out[idx] = out[idx] + g_agg1[idx] * invd + b1[f];
}

// ---------------------------------------------------------------------------
extern "C" void kernel_launch(void* const* d_in, const int* in_sizes, int n_in,
                              void* d_out, int out_size) {
    const float* x        = (const float*)d_in[0];
    const int*   src      = (const int*)d_in[1];
    const int*   dst      = (const int*)d_in[2];
    const float* W_self0  = (const float*)d_in[3];
    const float* W_neigh0 = (const float*)d_in[4];
    const float* b0       = (const float*)d_in[5];
    const float* W_self1  = (const float*)d_in[6];
    const float* W_neigh1 = (const float*)d_in[7];
    const float* b1       = (const float*)d_in[8];
    float* out = (float*)d_out;

    const int M = in_sizes[0] / F0;   // 50000
    const int E = in_sizes[1];        // 800000

    float* dY0; cudaGetSymbolAddress((void**)&dY0, g_Y0);
    float* dY1; cudaGetSymbolAddress((void**)&dY1, g_Y1);
    float* dH;  cudaGetSymbolAddress((void**)&dH,  g_h);

    // 0) zero accumulators + degree
    zero_all_kernel<<<2048, 256>>>();
    degree_kernel<<<(E + 255) / 256, 256>>>(dst, E);

    // 1) layer-0 GEMMs (tf32 tensor cores)
    dim3 thr(256);
    dim3 g0((M + 127) / 128, (F1 + 63) / 64);
    mma_gemm_kernel<false><<<g0, thr>>>(x, W_self0,  dH,  M, F1, F0);
    mma_gemm_kernel<false><<<g0, thr>>>(x, W_neigh0, dY0, M, F1, F0);

    // 2) layer-0 aggregation + finalize
    agg128_kernel<<<(E * 32 + 255) / 256, 256>>>(src, dst, E);
    finalize0_kernel<<<(M * (F1 / 4) + 255) / 256, 256>>>(b0);

    // 3) layer-1 GEMMs (N=41, guarded)
    dim3 g1((M + 127) / 128, (C1 + 63) / 64);
    mma_gemm_kernel<true><<<g1, thr>>>(dH, W_self1,  out, M, C1, F1);
    mma_gemm_kernel<true><<<g1, thr>>>(dH, W_neigh1, dY1, M, C1, F1);

    // 4) layer-1 aggregation + finalize
    agg41_kernel<<<(E * C1 + 255) / 256, 256>>>(src, dst, E);
    finalize1_kernel<<<(M * C1 + 255) / 256, 256>>>(out, b1);
}

// round 3
// speedup vs baseline: 3.2663x; 2.5296x over previous
#include <cuda_runtime.h>
#include <cstdint>

// SAGE_68281390072709 — 2-layer GraphSAGE, fp32.
// tf32 tensor-core GEMMs + CSR gather aggregation (no float atomics).

#define NN 50000
#define EE 800000
#define F0 128
#define F1 128
#define C1 41
#define SCAN_B 1024
#define SCAN_NB ((NN + SCAN_B - 1) / SCAN_B)   // 49

__device__ float g_Y0[NN * F1];
__device__ float g_h[NN * F1];
__device__ float g_Y1[NN * C1];
__device__ int   g_deg[NN];
__device__ int   g_rowptr[NN + 1];
__device__ int   g_cursor[NN];
__device__ int   g_csr_src[EE];
__device__ int   g_blksum[SCAN_NB];

// ---------------------------------------------------------------------------
// CSR construction
// ---------------------------------------------------------------------------
__global__ void zero_deg_kernel() {
    int i = blockIdx.x * blockDim.x + threadIdx.x;
    if (i < NN) g_deg[i] = 0;
}

__global__ void hist_kernel(const int* __restrict__ dst, int E) {
    int i = blockIdx.x * blockDim.x + threadIdx.x;
    if (i < E) atomicAdd(&g_deg[dst[i]], 1);
}

__global__ void scan_local_kernel() {
    __shared__ int s[SCAN_B];
    int tid = threadIdx.x;
    int i = blockIdx.x * SCAN_B + tid;
    int v = (i < NN) ? g_deg[i] : 0;
    s[tid] = v;
    __syncthreads();
#pragma unroll
    for (int off = 1; off < SCAN_B; off <<= 1) {
        int t = (tid >= off) ? s[tid - off] : 0;
        __syncthreads();
        if (tid >= off) s[tid] += t;
        __syncthreads();
    }
    if (i < NN) g_rowptr[i] = s[tid] - v;   // exclusive within block
    if (tid == SCAN_B - 1) g_blksum[blockIdx.x] = s[tid];
}

__global__ void scan_blk_kernel() {
    // single thread, 49 values: serial exclusive scan
    int run = 0;
    for (int b = 0; b < SCAN_NB; b++) {
        int v = g_blksum[b];
        g_blksum[b] = run;
        run += v;
    }
    g_rowptr[NN] = run;   // == E
}

__global__ void scan_add_kernel() {
    int i = blockIdx.x * blockDim.x + threadIdx.x;
    if (i < NN) {
        int r = g_rowptr[i] + g_blksum[i / SCAN_B];
        g_rowptr[i] = r;
        g_cursor[i] = r;
    }
}

__global__ void fill_kernel(const int* __restrict__ src,
                            const int* __restrict__ dst, int E) {
    int e = blockIdx.x * blockDim.x + threadIdx.x;
    if (e < E) {
        int pos = atomicAdd(&g_cursor[dst[e]], 1);
        g_csr_src[pos] = src[e];
    }
}

// ---------------------------------------------------------------------------
// tf32 tensor-core GEMM: C[M,N] = A[M,K] @ B[K,N]
// BM=128, BN=64, BK=16, 256 threads (8 warps), warp tile 32x32
// ---------------------------------------------------------------------------
__device__ __forceinline__ uint32_t f2tf32(float x) {
    uint32_t r;
    asm("cvt.rna.tf32.f32 %0, %1;" : "=r"(r) : "f"(x));
    return r;
}

__device__ __forceinline__ void mma_tf32(float* c, const uint32_t* a, const uint32_t* b) {
    asm volatile(
        "mma.sync.aligned.m16n8k8.row.col.f32.tf32.tf32.f32 "
        "{%0,%1,%2,%3}, {%4,%5,%6,%7}, {%8,%9}, {%0,%1,%2,%3};"
        : "+f"(c[0]), "+f"(c[1]), "+f"(c[2]), "+f"(c[3])
        : "r"(a[0]), "r"(a[1]), "r"(a[2]), "r"(a[3]), "r"(b[0]), "r"(b[1]));
}

template <bool GUARD_N>
__global__ void __launch_bounds__(256)
mma_gemm_kernel(const float* __restrict__ A, const float* __restrict__ B,
                float* __restrict__ C, int M, int N, int K) {
    constexpr int BM = 128, BN = 64, BK = 16;
    __shared__ uint32_t As[BM][BK + 4];
    __shared__ uint32_t Bs[BK][BN + 8];

    const int tid = threadIdx.x;
    const int lane = tid & 31;
    const int wid = tid >> 5;
    const int g = lane >> 2;
    const int t = lane & 3;
    const int wm = (wid >> 1) * 32;
    const int wn = (wid & 1) * 32;
    const int m0 = blockIdx.x * BM;
    const int n0 = blockIdx.y * BN;

    float acc[2][4][4];
#pragma unroll
    for (int mf = 0; mf < 2; mf++)
#pragma unroll
        for (int nf = 0; nf < 4; nf++)
#pragma unroll
            for (int i = 0; i < 4; i++) acc[mf][nf][i] = 0.f;

    for (int k0 = 0; k0 < K; k0 += BK) {
#pragma unroll
        for (int i = 0; i < 2; i++) {
            int v = tid + i * 256;
            int row = v >> 2;
            int c4 = (v & 3) * 4;
            float4 av = make_float4(0.f, 0.f, 0.f, 0.f);
            int gm = m0 + row;
            if (gm < M)
                av = *reinterpret_cast<const float4*>(A + (long)gm * K + k0 + c4);
            As[row][c4 + 0] = f2tf32(av.x);
            As[row][c4 + 1] = f2tf32(av.y);
            As[row][c4 + 2] = f2tf32(av.z);
            As[row][c4 + 3] = f2tf32(av.w);
        }
        {
            int row = tid >> 4;
            int c4 = (tid & 15) * 4;
            if (GUARD_N) {
#pragma unroll
                for (int j = 0; j < 4; j++) {
                    int gn = n0 + c4 + j;
                    float bv = (gn < N) ? B[(long)(k0 + row) * N + gn] : 0.f;
                    Bs[row][c4 + j] = f2tf32(bv);
                }
            } else {
                float4 bv = *reinterpret_cast<const float4*>(B + (long)(k0 + row) * N + n0 + c4);
                Bs[row][c4 + 0] = f2tf32(bv.x);
                Bs[row][c4 + 1] = f2tf32(bv.y);
                Bs[row][c4 + 2] = f2tf32(bv.z);
                Bs[row][c4 + 3] = f2tf32(bv.w);
            }
        }
        __syncthreads();

#pragma unroll
        for (int ks = 0; ks < BK; ks += 8) {
            uint32_t a[2][4], b[4][2];
#pragma unroll
            for (int mf = 0; mf < 2; mf++) {
                int r = wm + mf * 16;
                a[mf][0] = As[r + g][ks + t];
                a[mf][1] = As[r + g + 8][ks + t];
                a[mf][2] = As[r + g][ks + t + 4];
                a[mf][3] = As[r + g + 8][ks + t + 4];
            }
#pragma unroll
            for (int nf = 0; nf < 4; nf++) {
                int c = wn + nf * 8 + g;
                b[nf][0] = Bs[ks + t][c];
                b[nf][1] = Bs[ks + t + 4][c];
            }
#pragma unroll
            for (int mf = 0; mf < 2; mf++)
#pragma unroll
                for (int nf = 0; nf < 4; nf++)
                    mma_tf32(acc[mf][nf], a[mf], b[nf]);
        }
        __syncthreads();
    }

#pragma unroll
    for (int mf = 0; mf < 2; mf++) {
#pragma unroll
        for (int nf = 0; nf < 4; nf++) {
            int row0 = m0 + wm + mf * 16 + g;
            int col0 = n0 + wn + nf * 8 + 2 * t;
#pragma unroll
            for (int rr = 0; rr < 2; rr++) {
                int row = row0 + rr * 8;
                if (row >= M) continue;
                float* cp = C + (long)row * N + col0;
                if (!GUARD_N || col0 < N)     cp[0] = acc[mf][nf][rr * 2 + 0];
                if (!GUARD_N || col0 + 1 < N) cp[1] = acc[mf][nf][rr * 2 + 1];
            }
        }
    }
}

// ---------------------------------------------------------------------------
// layer-0 gather + finalize: warp per node.
// h[n] = relu(S0[n] + (sum_{s in N(n)} Y0[s]) / max(deg,1) + b0)
// S0 already resides in g_h.
// ---------------------------------------------------------------------------
__global__ void __launch_bounds__(256)
gather0_kernel(const float* __restrict__ b0) {
    int warp = (blockIdx.x * blockDim.x + threadIdx.x) >> 5;
    if (warp >= NN) return;
    int lane = threadIdx.x & 31;
    int beg = g_rowptr[warp];
    int end = g_rowptr[warp + 1];

    float4 acc = make_float4(0.f, 0.f, 0.f, 0.f);
    int e = beg;
    for (; e + 1 < end; e += 2) {
        int s0 = g_csr_src[e];
        int s1 = g_csr_src[e + 1];
        float4 v0 = *reinterpret_cast<const float4*>(g_Y0 + (long)s0 * F1 + lane * 4);
        float4 v1 = *reinterpret_cast<const float4*>(g_Y0 + (long)s1 * F1 + lane * 4);
        acc.x += v0.x + v1.x;
        acc.y += v0.y + v1.y;
        acc.z += v0.z + v1.z;
        acc.w += v0.w + v1.w;
    }
    if (e < end) {
        int s0 = g_csr_src[e];
        float4 v0 = *reinterpret_cast<const float4*>(g_Y0 + (long)s0 * F1 + lane * 4);
        acc.x += v0.x; acc.y += v0.y; acc.z += v0.z; acc.w += v0.w;
    }

    float invd = 1.0f / fmaxf((float)(end - beg), 1.0f);
    float4 h = *reinterpret_cast<const float4*>(g_h + (long)warp * F1 + lane * 4);
    float4 b = *reinterpret_cast<const float4*>(b0 + lane * 4);
    h.x = fmaxf(h.x + acc.x * invd + b.x, 0.f);
    h.y = fmaxf(h.y + acc.y * invd + b.y, 0.f);
    h.z = fmaxf(h.z + acc.z * invd + b.z, 0.f);
    h.w = fmaxf(h.w + acc.w * invd + b.w, 0.f);
    *reinterpret_cast<float4*>(g_h + (long)warp * F1 + lane * 4) = h;
}

// ---------------------------------------------------------------------------
// layer-1 gather + finalize: warp per node, 41 features.
// out[n] = S1[n] + (sum Y1[s]) / max(deg,1) + b1  (S1 already in out)
// lane handles feature `lane`; lanes 0..8 also handle `lane+32`.
// ---------------------------------------------------------------------------
__global__ void __launch_bounds__(256)
gather1_kernel(float* __restrict__ out, const float* __restrict__ b1) {
    int warp = (blockIdx.x * blockDim.x + threadIdx.x) >> 5;
    if (warp >= NN) return;
    int lane = threadIdx.x & 31;
    int beg = g_rowptr[warp];
    int end = g_rowptr[warp + 1];
    bool hi = (lane < C1 - 32);   // lanes 0..8

    float acc0 = 0.f, acc1 = 0.f;
    int e = beg;
    for (; e + 1 < end; e += 2) {
        int s0 = g_csr_src[e];
        int s1 = g_csr_src[e + 1];
        const float* r0 = g_Y1 + (long)s0 * C1;
        const float* r1 = g_Y1 + (long)s1 * C1;
        acc0 += r0[lane] + r1[lane];
        if (hi) acc1 += r0[lane + 32] + r1[lane + 32];
    }
    if (e < end) {
        const float* r0 = g_Y1 + (long)g_csr_src[e] * C1;
        acc0 += r0[lane];
        if (hi) acc1 += r0[lane + 32];
    }

    float invd = 1.0f / fmaxf((float)(end - beg), 1.0f);
    float* o = out + (long)warp * C1;
    o[lane] = o[lane] + acc0 * invd + b1[lane];
    if (hi) o[lane + 32] = o[lane + 32] + acc1 * invd + b1[lane + 32];
}

// ---------------------------------------------------------------------------
extern "C" void kernel_launch(void* const* d_in, const int* in_sizes, int n_in,
                              void* d_out, int out_size) {
    const float* x        = (const float*)d_in[0];
    const int*   src      = (const int*)d_in[1];
    const int*   dst      = (const int*)d_in[2];
    const float* W_self0  = (const float*)d_in[3];
    const float* W_neigh0 = (const float*)d_in[4];
    const float* b0       = (const float*)d_in[5];
    const float* W_self1  = (const float*)d_in[6];
    const float* W_neigh1 = (const float*)d_in[7];
    const float* b1       = (const float*)d_in[8];
    float* out = (float*)d_out;

    const int M = in_sizes[0] / F0;   // 50000
    const int E = in_sizes[1];        // 800000

    float* dY0; cudaGetSymbolAddress((void**)&dY0, g_Y0);
    float* dY1; cudaGetSymbolAddress((void**)&dY1, g_Y1);
    float* dH;  cudaGetSymbolAddress((void**)&dH,  g_h);

    // --- CSR build (by dst) ---
    zero_deg_kernel<<<(NN + 255) / 256, 256>>>();
    hist_kernel<<<(E + 255) / 256, 256>>>(dst, E);
    scan_local_kernel<<<SCAN_NB, SCAN_B>>>();
    scan_blk_kernel<<<1, 1>>>();
    scan_add_kernel<<<(NN + 255) / 256, 256>>>();
    fill_kernel<<<(E + 255) / 256, 256>>>(src, dst, E);

    // --- layer-0 GEMMs ---
    dim3 thr(256);
    dim3 g0((M + 127) / 128, (F1 + 63) / 64);
    mma_gemm_kernel<false><<<g0, thr>>>(x, W_self0,  dH,  M, F1, F0);
    mma_gemm_kernel<false><<<g0, thr>>>(x, W_neigh0, dY0, M, F1, F0);

    // --- layer-0 gather + finalize (relu fused) ---
    gather0_kernel<<<(NN * 32 + 255) / 256, 256>>>(b0);

    // --- layer-1 GEMMs ---
    dim3 g1((M + 127) / 128, (C1 + 63) / 64);
    mma_gemm_kernel<true><<<g1, thr>>>(dH, W_self1,  out, M, C1, F1);
    mma_gemm_kernel<true><<<g1, thr>>>(dH, W_neigh1, dY1, M, C1, F1);

    // --- layer-1 gather + finalize ---
    gather1_kernel<<<(NN * 32 + 255) / 256, 256>>>(out, b1);
}